// round 5
// baseline (speedup 1.0000x reference)
#include <cuda_runtime.h>
#include <cuda_bf16.h>
#include <cstdint>
#include <cstddef>
#include <math.h>

#define THREADS 256
#define MROWS   64

// smem byte offsets (dynamic)
// phase1: X @0 (768), W1P @768 (4096). phase2 (after layer1): WC @0 (4096).
#define OFF_X     0
#define OFF_W1P   768
#define OFF_WC    0
#define OFF_AHI   5120     // 64*512 = 32768
#define OFF_ALO   37888    // 32768
#define OFF_B     70656    // 2 bufs * 20480
#define BBUF      20480    // 256 rows * 80 B (hi 32B | lo 32B | pad 16B)
#define OFF_ZP    OFF_B    // aliased over B buf0 in epilogue (last chunk reads buf1)
#define SMEM_TOTAL 111616

__device__ __nv_bfloat16 g_w2hi[65536];
__device__ __nv_bfloat16 g_w2lo[65536];

__device__ __forceinline__ void cp_async16(void* dst, const void* src) {
    uint32_t d;
    asm("{ .reg .u64 t; cvta.to.shared.u64 t, %1; cvt.u32.u64 %0, t; }" : "=r"(d) : "l"(dst));
    asm volatile("cp.async.cg.shared.global [%0], [%1], 16;" :: "r"(d), "l"(src) : "memory");
}
__device__ __forceinline__ void cp_commit() { asm volatile("cp.async.commit_group;" ::: "memory"); }
__device__ __forceinline__ void cp_wait1()  { asm volatile("cp.async.wait_group 1;" ::: "memory"); }
__device__ __forceinline__ void cp_wait0()  { asm volatile("cp.async.wait_group 0;" ::: "memory"); }

__device__ __forceinline__ void mma_bf16(float* d, const uint32_t* a, uint32_t b0, uint32_t b1) {
    asm volatile(
        "mma.sync.aligned.m16n8k16.row.col.f32.bf16.bf16.f32 "
        "{%0,%1,%2,%3}, {%4,%5,%6,%7}, {%8,%9}, {%0,%1,%2,%3};"
        : "+f"(d[0]), "+f"(d[1]), "+f"(d[2]), "+f"(d[3])
        : "r"(a[0]), "r"(a[1]), "r"(a[2]), "r"(a[3]), "r"(b0), "r"(b1));
}

// ---------------- pre-kernel: split w2 into bf16 hi/lo ----------------
__global__ void w2_split_kernel(const float* __restrict__ w2) {
    int i = blockIdx.x * 256 + threadIdx.x;
    float v = w2[i];
    __nv_bfloat16 hp = __float2bfloat16(v);
    g_w2hi[i] = hp;
    g_w2lo[i] = __float2bfloat16(v - __bfloat162float(hp));
}

// ---------------- main fused kernel ----------------
__global__ __launch_bounds__(THREADS, 2)
void dpl_hmma_kernel(const float* __restrict__ x,
                     const float* __restrict__ w1,
                     const float* __restrict__ b1,
                     const float* __restrict__ b2,
                     const float* __restrict__ w3,
                     const float* __restrict__ b3,
                     float* __restrict__ out,
                     int Btot, int write_logits)
{
    extern __shared__ char smc[];
    const int tid  = threadIdx.x;
    const int wid  = tid >> 5;       // 0..7
    const int lane = tid & 31;
    const int row0 = blockIdx.x * MROWS;

    const int rg  = wid & 1;         // row group: rows rg*32..+31
    const int cg  = wid >> 1;        // col group: cols cg*64..+63
    const int g   = lane >> 2;       // 0..7
    const int tig = lane & 3;        // 0..3

    // ---- stage x + packed w1/b1 ----
    {
        float* sX = (float*)(smc + OFF_X);
        for (int i = tid; i < MROWS * 3; i += THREADS) {
            long gi = (long)row0 * 3 + i;
            sX[i] = (gi < (long)Btot * 3) ? x[gi] : 0.0f;
        }
        ((float4*)(smc + OFF_W1P))[tid] =
            make_float4(w1[tid*3+0], w1[tid*3+1], w1[tid*3+2], b1[tid]);
    }
    __syncthreads();

    // ---- layer 1 -> A hi/lo bf16 tiles (XOR-swizzled, conflict-free) ----
    {
        const float*  sX   = (const float*)(smc + OFF_X);
        const float4* sW1P = (const float4*)(smc + OFF_W1P);
        const int r = wid * 8 + (lane & 7);          // warp w -> rows w*8..+7
        const int jb = (lane >> 3) << 1;             // 0,2,4,6
        const uint32_t xorv = (uint32_t)((lane & 7) << 4);
        const float x0 = sX[r*3+0], x1 = sX[r*3+1], x2 = sX[r*3+2];
        char* rowhi = smc + OFF_AHI + r * 512;
        char* rowlo = smc + OFF_ALO + r * 512;
        #pragma unroll 8
        for (int t = 0; t < 32; t++) {
            const int j = jb + t * 8;
            float4 wa = sW1P[j];
            float4 wb = sW1P[j+1];
            float f0 = fmaf(x0, wa.x, fmaf(x1, wa.y, fmaf(x2, wa.z, wa.w)));
            float f1 = fmaf(x0, wb.x, fmaf(x1, wb.y, fmaf(x2, wb.z, wb.w)));
            f0 = fmaxf(f0, 0.0f); f1 = fmaxf(f1, 0.0f);
            __nv_bfloat16 h0 = __float2bfloat16(f0);
            __nv_bfloat16 h1 = __float2bfloat16(f1);
            __nv_bfloat162 hw; hw.x = h0; hw.y = h1;
            __nv_bfloat162 lw = __floats2bfloat162_rn(f0 - __bfloat162float(h0),
                                                      f1 - __bfloat162float(h1));
            const uint32_t off = (uint32_t)(j * 2) ^ xorv;
            *(uint32_t*)(rowhi + off) = *(uint32_t*)&hw;
            *(uint32_t*)(rowlo + off) = *(uint32_t*)&lw;
        }
    }
    __syncthreads();

    // ---- stage WC (b2 | w3 rows) into aliased region; X/W1P dead now ----
    ((float4*)(smc + OFF_WC))[tid] =
        make_float4(b2[tid], w3[tid], w3[256+tid], w3[512+tid]);

    // ---- preload B chunk 0: row n = tid, [hi 32B | lo 32B] ----
    {
        const char* hi = (const char*)g_w2hi + (size_t)tid * 512;
        const char* lo = (const char*)g_w2lo + (size_t)tid * 512;
        char* dst = smc + OFF_B + tid * 80;
        cp_async16(dst +  0, hi +  0);
        cp_async16(dst + 16, hi + 16);
        cp_async16(dst + 32, lo +  0);
        cp_async16(dst + 48, lo + 16);
        cp_commit();
    }

    // ---- accumulators ----
    float acc[2][8][4];
    #pragma unroll
    for (int mt = 0; mt < 2; mt++)
        #pragma unroll
        for (int nt = 0; nt < 8; nt++)
            #pragma unroll
            for (int q = 0; q < 4; q++) acc[mt][nt][q] = 0.0f;

    const uint32_t axor = (uint32_t)(g << 4);
    const char* arowhi0 = smc + OFF_AHI + (rg * 32 + g) * 512;
    const char* arowlo0 = smc + OFF_ALO + (rg * 32 + g) * 512;

    // ---- main loop: 16 chunks of k=16 ----
    for (int c = 0; c < 16; c++) {
        if (c < 15) {
            const int nxt = c + 1;
            const char* hi = (const char*)g_w2hi + (size_t)tid * 512 + nxt * 32;
            const char* lo = (const char*)g_w2lo + (size_t)tid * 512 + nxt * 32;
            char* dst = smc + OFF_B + (nxt & 1) * BBUF + tid * 80;
            cp_async16(dst +  0, hi +  0);
            cp_async16(dst + 16, hi + 16);
            cp_async16(dst + 32, lo +  0);
            cp_async16(dst + 48, lo + 16);
            cp_commit();
            cp_wait1();
        } else {
            cp_wait0();
        }
        __syncthreads();

        const char* bb = smc + OFF_B + (c & 1) * BBUF;
        const uint32_t koffL = ((uint32_t)((c * 16 + tig * 2) * 2)) ^ axor;
        const uint32_t koffH = ((uint32_t)((c * 16 + tig * 2 + 8) * 2)) ^ axor;

        uint32_t ahi[2][4], alo[2][4];
        #pragma unroll
        for (int mt = 0; mt < 2; mt++) {
            const int ro = mt * 16 * 512;
            ahi[mt][0] = *(const uint32_t*)(arowhi0 + ro + koffL);
            ahi[mt][1] = *(const uint32_t*)(arowhi0 + ro + 8*512 + koffL);
            ahi[mt][2] = *(const uint32_t*)(arowhi0 + ro + koffH);
            ahi[mt][3] = *(const uint32_t*)(arowhi0 + ro + 8*512 + koffH);
            alo[mt][0] = *(const uint32_t*)(arowlo0 + ro + koffL);
            alo[mt][1] = *(const uint32_t*)(arowlo0 + ro + 8*512 + koffL);
            alo[mt][2] = *(const uint32_t*)(arowlo0 + ro + koffH);
            alo[mt][3] = *(const uint32_t*)(arowlo0 + ro + 8*512 + koffH);
        }

        // nt in pairs: 4 independent MMAs per pass before any acc revisit
        #pragma unroll
        for (int ntp = 0; ntp < 4; ntp++) {
            const int nt0 = ntp * 2, nt1 = nt0 + 1;
            const char* brow0 = bb + (cg * 64 + nt0 * 8 + g) * 80;
            const char* brow1 = bb + (cg * 64 + nt1 * 8 + g) * 80;
            uint32_t b0h0 = *(const uint32_t*)(brow0 + tig*4);
            uint32_t b0h1 = *(const uint32_t*)(brow0 + tig*4 + 16);
            uint32_t b1h0 = *(const uint32_t*)(brow1 + tig*4);
            uint32_t b1h1 = *(const uint32_t*)(brow1 + tig*4 + 16);
            // pass 1: Ahi * Bhi
            mma_bf16(acc[0][nt0], ahi[0], b0h0, b0h1);
            mma_bf16(acc[1][nt0], ahi[1], b0h0, b0h1);
            mma_bf16(acc[0][nt1], ahi[0], b1h0, b1h1);
            mma_bf16(acc[1][nt1], ahi[1], b1h0, b1h1);
            // pass 2: Alo * Bhi
            mma_bf16(acc[0][nt0], alo[0], b0h0, b0h1);
            mma_bf16(acc[1][nt0], alo[1], b0h0, b0h1);
            mma_bf16(acc[0][nt1], alo[0], b1h0, b1h1);
            mma_bf16(acc[1][nt1], alo[1], b1h0, b1h1);
            // pass 3: Ahi * Blo
            uint32_t b0l0 = *(const uint32_t*)(brow0 + 32 + tig*4);
            uint32_t b0l1 = *(const uint32_t*)(brow0 + 48 + tig*4);
            uint32_t b1l0 = *(const uint32_t*)(brow1 + 32 + tig*4);
            uint32_t b1l1 = *(const uint32_t*)(brow1 + 48 + tig*4);
            mma_bf16(acc[0][nt0], ahi[0], b0l0, b0l1);
            mma_bf16(acc[1][nt0], ahi[1], b0l0, b0l1);
            mma_bf16(acc[0][nt1], ahi[0], b1l0, b1l1);
            mma_bf16(acc[1][nt1], ahi[1], b1l0, b1l1);
        }
        __syncthreads();
    }

    // ---- epilogue: relu(+b2) + layer3 partials in registers ----
    const float4* sWC = (const float4*)(smc + OFF_WC);
    float z[4][3];
    #pragma unroll
    for (int i = 0; i < 4; i++) { z[i][0] = 0.f; z[i][1] = 0.f; z[i][2] = 0.f; }

    #pragma unroll
    for (int mt = 0; mt < 2; mt++) {
        #pragma unroll
        for (int nt = 0; nt < 8; nt++) {
            const int j0 = cg * 64 + nt * 8 + tig * 2;
            float4 wc0 = sWC[j0];
            float4 wc1 = sWC[j0 + 1];
            float h;
            h = fmaxf(acc[mt][nt][0] + wc0.x, 0.0f);
            z[mt*2][0] = fmaf(h, wc0.y, z[mt*2][0]);
            z[mt*2][1] = fmaf(h, wc0.z, z[mt*2][1]);
            z[mt*2][2] = fmaf(h, wc0.w, z[mt*2][2]);
            h = fmaxf(acc[mt][nt][1] + wc1.x, 0.0f);
            z[mt*2][0] = fmaf(h, wc1.y, z[mt*2][0]);
            z[mt*2][1] = fmaf(h, wc1.z, z[mt*2][1]);
            z[mt*2][2] = fmaf(h, wc1.w, z[mt*2][2]);
            h = fmaxf(acc[mt][nt][2] + wc0.x, 0.0f);
            z[mt*2+1][0] = fmaf(h, wc0.y, z[mt*2+1][0]);
            z[mt*2+1][1] = fmaf(h, wc0.z, z[mt*2+1][1]);
            z[mt*2+1][2] = fmaf(h, wc0.w, z[mt*2+1][2]);
            h = fmaxf(acc[mt][nt][3] + wc1.x, 0.0f);
            z[mt*2+1][0] = fmaf(h, wc1.y, z[mt*2+1][0]);
            z[mt*2+1][1] = fmaf(h, wc1.z, z[mt*2+1][1]);
            z[mt*2+1][2] = fmaf(h, wc1.w, z[mt*2+1][2]);
        }
    }
    // reduce across the 4 tig lanes of each quad
    #pragma unroll
    for (int i = 0; i < 4; i++)
        #pragma unroll
        for (int cmp = 0; cmp < 3; cmp++) {
            float v = z[i][cmp];
            v += __shfl_xor_sync(0xffffffffu, v, 1);
            v += __shfl_xor_sync(0xffffffffu, v, 2);
            z[i][cmp] = v;
        }

    // partials per col-group into smem (aliased over B buf0; last chunk read buf1)
    if (tig == 0) {
        float4* sZP = (float4*)(smc + OFF_ZP);
        #pragma unroll
        for (int i = 0; i < 4; i++) {
            const int r = rg * 32 + (i >> 1) * 16 + (i & 1) * 8 + g;
            sZP[cg * MROWS + r] = make_float4(z[i][0], z[i][1], z[i][2], 0.0f);
        }
    }
    __syncthreads();

    if (tid < MROWS) {
        const float4* sZP = (const float4*)(smc + OFF_ZP);
        float4 a0 = sZP[tid], a1 = sZP[64 + tid], a2 = sZP[128 + tid], a3 = sZP[192 + tid];
        float z0 = a0.x + a1.x + a2.x + a3.x + b3[0];
        float z1 = a0.y + a1.y + a2.y + a3.y + b3[1];
        float z2 = a0.z + a1.z + a2.z + a3.z + b3[2];

        const int gr = row0 + tid;
        if (gr < Btot) {
            const float eps  = 1e-5f;
            const float norm = 1.0f / (1.0f + 2.0f * eps);
            float s0 = 1.0f / (1.0f + expf(-z0));
            float s1 = 1.0f / (1.0f + expf(-z1));
            float s2 = 1.0f / (1.0f + expf(-z2));
            float pp0 = (s0 + eps) * norm, pn0 = (1.0f - s0 + eps) * norm;
            float pp1 = (s1 + eps) * norm, pn1 = (1.0f - s1 + eps) * norm;
            float pp2 = (s2 + eps) * norm, pn2 = (1.0f - s2 + eps) * norm;
            float pred1 = pn0*pn1*pp2 + pn0*pp1*pn2 + pp0*pn1*pn2 + pp0*pp1*pp2;
            float pred0 = 1.0f - pred1;
            const float onorm = 1.0f / 1.002f;
            float2 pr = make_float2((pred0 + 0.001f) * onorm, (pred1 + 0.001f) * onorm);
            *(float2*)&out[(size_t)gr * 2] = pr;
            if (write_logits) {
                float* outLg = &out[(size_t)2 * Btot + (size_t)gr * 3];
                outLg[0] = z0; outLg[1] = z1; outLg[2] = z2;
            }
        }
    }
}

extern "C" void kernel_launch(void* const* d_in, const int* in_sizes, int n_in,
                              void* d_out, int out_size)
{
    const float* x  = (const float*)d_in[0];
    const float* w1 = (const float*)d_in[1];
    const float* b1 = (const float*)d_in[2];
    const float* w2 = (const float*)d_in[3];
    const float* b2 = (const float*)d_in[4];
    const float* w3 = (const float*)d_in[5];
    const float* b3 = (const float*)d_in[6];
    float* out = (float*)d_out;

    const int B = in_sizes[0] / 3;
    const int write_logits = (out_size >= 5 * B) ? 1 : 0;

    w2_split_kernel<<<256, 256>>>(w2);

    cudaFuncSetAttribute(dpl_hmma_kernel,
                         cudaFuncAttributeMaxDynamicSharedMemorySize, SMEM_TOTAL);

    const int grid = (B + MROWS - 1) / MROWS;
    dpl_hmma_kernel<<<grid, THREADS, SMEM_TOTAL>>>(x, w1, b1, b2, w3, b3,
                                                   out, B, write_logits);
}

// round 6
// speedup vs baseline: 2.7590x; 2.7590x over previous
#include <cuda_runtime.h>
#include <cuda_fp16.h>
#include <cstdint>
#include <cstddef>
#include <math.h>

#define THREADS 512
#define MROWS   128

// smem byte offsets (dynamic)
#define OFF_X     0        // 128*3*4 = 1536
#define OFF_W1P   1536     // 256*16  = 4096
#define OFF_WC    5632     // 256*16  = 4096
#define OFF_ZP    9728     // 4*128*16 = 8192
#define OFF_A     18432    // 128 rows * 512 B (256 fp16) = 65536
#define OFF_B     83968    // 2 bufs * 20480
#define BBUF      20480    // 256 rows * 80 B (64B data + 16B pad)
#define SMEM_TOTAL 124928

__device__ __half g_w2h[65536];

__device__ __forceinline__ void cp_async16(void* dst, const void* src) {
    uint32_t d;
    asm("{ .reg .u64 t; cvta.to.shared.u64 t, %1; cvt.u32.u64 %0, t; }" : "=r"(d) : "l"(dst));
    asm volatile("cp.async.cg.shared.global [%0], [%1], 16;" :: "r"(d), "l"(src) : "memory");
}
__device__ __forceinline__ void cp_commit() { asm volatile("cp.async.commit_group;" ::: "memory"); }
__device__ __forceinline__ void cp_wait1()  { asm volatile("cp.async.wait_group 1;" ::: "memory"); }
__device__ __forceinline__ void cp_wait0()  { asm volatile("cp.async.wait_group 0;" ::: "memory"); }

__device__ __forceinline__ void mma_f16(float* d, const uint32_t* a, uint32_t b0, uint32_t b1) {
    asm volatile(
        "mma.sync.aligned.m16n8k16.row.col.f32.f16.f16.f32 "
        "{%0,%1,%2,%3}, {%4,%5,%6,%7}, {%8,%9}, {%0,%1,%2,%3};"
        : "+f"(d[0]), "+f"(d[1]), "+f"(d[2]), "+f"(d[3])
        : "r"(a[0]), "r"(a[1]), "r"(a[2]), "r"(a[3]), "r"(b0), "r"(b1));
}

// ---------------- pre-kernel: convert w2 to fp16 ----------------
__global__ void w2_half_kernel(const float* __restrict__ w2) {
    int i = blockIdx.x * 256 + threadIdx.x;
    g_w2h[i] = __float2half_rn(w2[i]);
}

// ---------------- main fused kernel ----------------
__global__ __launch_bounds__(THREADS, 1)
void dpl_hmma_kernel(const float* __restrict__ x,
                     const float* __restrict__ w1,
                     const float* __restrict__ b1,
                     const float* __restrict__ b2,
                     const float* __restrict__ w3,
                     const float* __restrict__ b3,
                     float* __restrict__ out,
                     int Btot, int write_logits)
{
    extern __shared__ char smc[];
    const int tid  = threadIdx.x;
    const int wid  = tid >> 5;
    const int lane = tid & 31;
    const int row0 = blockIdx.x * MROWS;

    const int rg  = wid & 3;       // row group: rows rg*32..+31
    const int cg  = wid >> 2;      // col group: cols cg*64..+63
    const int g   = lane >> 2;     // 0..7
    const int tig = lane & 3;      // 0..3

    // ---- stage params + x ----
    {
        float* sX = (float*)(smc + OFF_X);
        for (int i = tid; i < MROWS * 3; i += THREADS) {
            long gi = (long)row0 * 3 + i;
            sX[i] = (gi < (long)Btot * 3) ? x[gi] : 0.0f;
        }
        if (tid < 256) {
            ((float4*)(smc + OFF_W1P))[tid] =
                make_float4(w1[tid*3+0], w1[tid*3+1], w1[tid*3+2], b1[tid]);
            ((float4*)(smc + OFF_WC))[tid] =
                make_float4(b2[tid], w3[tid], w3[256+tid], w3[512+tid]);
        }
    }
    __syncthreads();

    // ---- layer 1 -> A fp16 tile (XOR-swizzled, conflict-free) ----
    {
        const float*  sX   = (const float*)(smc + OFF_X);
        const float4* sW1P = (const float4*)(smc + OFF_W1P);
        const int rb = (wid & 3) * 32 + (lane & 7);
        const int jb = (wid >> 2) * 64 + ((lane >> 3) << 1);
        const uint32_t xorv = (uint32_t)((lane & 7) << 4);
        #pragma unroll
        for (int s = 0; s < 4; s++) {
            const int r = rb + s * 8;
            const float x0 = sX[r*3+0], x1 = sX[r*3+1], x2 = sX[r*3+2];
            char* rowp = smc + OFF_A + r * 512;
            #pragma unroll
            for (int t = 0; t < 8; t++) {
                const int j = jb + t * 8;
                float4 wa = sW1P[j];
                float4 wb = sW1P[j+1];
                float f0 = fmaf(x0, wa.x, fmaf(x1, wa.y, fmaf(x2, wa.z, wa.w)));
                float f1 = fmaf(x0, wb.x, fmaf(x1, wb.y, fmaf(x2, wb.z, wb.w)));
                f0 = fmaxf(f0, 0.0f); f1 = fmaxf(f1, 0.0f);
                __half2 hw = __floats2half2_rn(f0, f1);
                const uint32_t off = (uint32_t)(j * 2) ^ xorv;
                *(uint32_t*)(rowp + off) = *(uint32_t*)&hw;
            }
        }
    }

    // ---- preload B chunk 0 (k=0..31 of all 256 n-rows) ----
    {
        #pragma unroll
        for (int it = 0; it < 2; it++) {
            int idx = tid + it * THREADS;     // 0..1023
            int n   = idx >> 2;
            int seg = idx & 3;
            const char* src = (const char*)g_w2h + (size_t)n * 512 + seg * 16;
            cp_async16(smc + OFF_B + n * 80 + seg * 16, src);
        }
        cp_commit();
    }

    // ---- accumulators ----
    float acc[2][8][4];
    #pragma unroll
    for (int mt = 0; mt < 2; mt++)
        #pragma unroll
        for (int nt = 0; nt < 8; nt++)
            #pragma unroll
            for (int q = 0; q < 4; q++) acc[mt][nt][q] = 0.0f;

    const uint32_t axor = (uint32_t)(g << 4);
    const char* arow0 = smc + OFF_A + (rg * 32 + g) * 512;

    // ---- main loop: 8 chunks of k=32 ----
    for (int c = 0; c < 8; c++) {
        if (c < 7) {
            const int nxt = c + 1;
            #pragma unroll
            for (int it = 0; it < 2; it++) {
                int idx = tid + it * THREADS;
                int n   = idx >> 2;
                int seg = idx & 3;
                const char* src = (const char*)g_w2h + (size_t)n * 512 + nxt * 64 + seg * 16;
                cp_async16(smc + OFF_B + (nxt & 1) * BBUF + n * 80 + seg * 16, src);
            }
            cp_commit();
            cp_wait1();
        } else {
            cp_wait0();
        }
        __syncthreads();

        const char* bb = smc + OFF_B + (c & 1) * BBUF;

        #pragma unroll
        for (int ks = 0; ks < 2; ks++) {
            const int kg = c * 32 + ks * 16;
            const uint32_t koffL = ((uint32_t)((kg + tig * 2) * 2)) ^ axor;
            const uint32_t koffH = ((uint32_t)((kg + tig * 2 + 8) * 2)) ^ axor;

            uint32_t afr[2][4];
            #pragma unroll
            for (int mt = 0; mt < 2; mt++) {
                const int ro = mt * 16 * 512;
                afr[mt][0] = *(const uint32_t*)(arow0 + ro + koffL);
                afr[mt][1] = *(const uint32_t*)(arow0 + ro + 8*512 + koffL);
                afr[mt][2] = *(const uint32_t*)(arow0 + ro + koffH);
                afr[mt][3] = *(const uint32_t*)(arow0 + ro + 8*512 + koffH);
            }

            // 16 independent MMAs per ks (each accumulator touched once)
            #pragma unroll
            for (int ntp = 0; ntp < 4; ntp++) {
                const int nt0 = ntp * 2, nt1 = nt0 + 1;
                const char* brow0 = bb + (cg * 64 + nt0 * 8 + g) * 80 + ks * 32;
                const char* brow1 = bb + (cg * 64 + nt1 * 8 + g) * 80 + ks * 32;
                uint32_t b00 = *(const uint32_t*)(brow0 + tig * 4);
                uint32_t b01 = *(const uint32_t*)(brow0 + tig * 4 + 16);
                uint32_t b10 = *(const uint32_t*)(brow1 + tig * 4);
                uint32_t b11 = *(const uint32_t*)(brow1 + tig * 4 + 16);
                mma_f16(acc[0][nt0], afr[0], b00, b01);
                mma_f16(acc[1][nt0], afr[1], b00, b01);
                mma_f16(acc[0][nt1], afr[0], b10, b11);
                mma_f16(acc[1][nt1], afr[1], b10, b11);
            }
        }
        __syncthreads();
    }

    // ---- epilogue: relu(+b2) + layer3 partials in registers ----
    const float4* sWC = (const float4*)(smc + OFF_WC);
    float z[4][3];
    #pragma unroll
    for (int i = 0; i < 4; i++) { z[i][0] = 0.f; z[i][1] = 0.f; z[i][2] = 0.f; }

    #pragma unroll
    for (int mt = 0; mt < 2; mt++) {
        #pragma unroll
        for (int nt = 0; nt < 8; nt++) {
            const int j0 = cg * 64 + nt * 8 + tig * 2;
            float4 wc0 = sWC[j0];
            float4 wc1 = sWC[j0 + 1];
            float h;
            h = fmaxf(acc[mt][nt][0] + wc0.x, 0.0f);
            z[mt*2][0] = fmaf(h, wc0.y, z[mt*2][0]);
            z[mt*2][1] = fmaf(h, wc0.z, z[mt*2][1]);
            z[mt*2][2] = fmaf(h, wc0.w, z[mt*2][2]);
            h = fmaxf(acc[mt][nt][1] + wc1.x, 0.0f);
            z[mt*2][0] = fmaf(h, wc1.y, z[mt*2][0]);
            z[mt*2][1] = fmaf(h, wc1.z, z[mt*2][1]);
            z[mt*2][2] = fmaf(h, wc1.w, z[mt*2][2]);
            h = fmaxf(acc[mt][nt][2] + wc0.x, 0.0f);
            z[mt*2+1][0] = fmaf(h, wc0.y, z[mt*2+1][0]);
            z[mt*2+1][1] = fmaf(h, wc0.z, z[mt*2+1][1]);
            z[mt*2+1][2] = fmaf(h, wc0.w, z[mt*2+1][2]);
            h = fmaxf(acc[mt][nt][3] + wc1.x, 0.0f);
            z[mt*2+1][0] = fmaf(h, wc1.y, z[mt*2+1][0]);
            z[mt*2+1][1] = fmaf(h, wc1.z, z[mt*2+1][1]);
            z[mt*2+1][2] = fmaf(h, wc1.w, z[mt*2+1][2]);
        }
    }
    // reduce across the 4 tig lanes of each quad
    #pragma unroll
    for (int i = 0; i < 4; i++)
        #pragma unroll
        for (int cmp = 0; cmp < 3; cmp++) {
            float v = z[i][cmp];
            v += __shfl_xor_sync(0xffffffffu, v, 1);
            v += __shfl_xor_sync(0xffffffffu, v, 2);
            z[i][cmp] = v;
        }

    if (tig == 0) {
        float4* sZP = (float4*)(smc + OFF_ZP);
        #pragma unroll
        for (int i = 0; i < 4; i++) {
            const int r = rg * 32 + (i >> 1) * 16 + (i & 1) * 8 + g;
            sZP[cg * 128 + r] = make_float4(z[i][0], z[i][1], z[i][2], 0.0f);
        }
    }
    __syncthreads();

    if (tid < MROWS) {
        const float4* sZP = (const float4*)(smc + OFF_ZP);
        float4 a0 = sZP[tid], a1 = sZP[128 + tid], a2 = sZP[256 + tid], a3 = sZP[384 + tid];
        float z0 = a0.x + a1.x + a2.x + a3.x + b3[0];
        float z1 = a0.y + a1.y + a2.y + a3.y + b3[1];
        float z2 = a0.z + a1.z + a2.z + a3.z + b3[2];

        const int gr = row0 + tid;
        if (gr < Btot) {
            const float eps  = 1e-5f;
            const float norm = 1.0f / (1.0f + 2.0f * eps);
            float s0 = 1.0f / (1.0f + expf(-z0));
            float s1 = 1.0f / (1.0f + expf(-z1));
            float s2 = 1.0f / (1.0f + expf(-z2));
            float pp0 = (s0 + eps) * norm, pn0 = (1.0f - s0 + eps) * norm;
            float pp1 = (s1 + eps) * norm, pn1 = (1.0f - s1 + eps) * norm;
            float pp2 = (s2 + eps) * norm, pn2 = (1.0f - s2 + eps) * norm;
            float pred1 = pn0*pn1*pp2 + pn0*pp1*pn2 + pp0*pn1*pn2 + pp0*pp1*pp2;
            float pred0 = 1.0f - pred1;
            const float onorm = 1.0f / 1.002f;
            float2 pr = make_float2((pred0 + 0.001f) * onorm, (pred1 + 0.001f) * onorm);
            *(float2*)&out[(size_t)gr * 2] = pr;
            if (write_logits) {
                float* outLg = &out[(size_t)2 * Btot + (size_t)gr * 3];
                outLg[0] = z0; outLg[1] = z1; outLg[2] = z2;
            }
        }
    }
}

extern "C" void kernel_launch(void* const* d_in, const int* in_sizes, int n_in,
                              void* d_out, int out_size)
{
    const float* x  = (const float*)d_in[0];
    const float* w1 = (const float*)d_in[1];
    const float* b1 = (const float*)d_in[2];
    const float* w2 = (const float*)d_in[3];
    const float* b2 = (const float*)d_in[4];
    const float* w3 = (const float*)d_in[5];
    const float* b3 = (const float*)d_in[6];
    float* out = (float*)d_out;

    const int B = in_sizes[0] / 3;
    const int write_logits = (out_size >= 5 * B) ? 1 : 0;

    w2_half_kernel<<<256, 256>>>(w2);

    cudaFuncSetAttribute(dpl_hmma_kernel,
                         cudaFuncAttributeMaxDynamicSharedMemorySize, SMEM_TOTAL);

    const int grid = (B + MROWS - 1) / MROWS;
    dpl_hmma_kernel<<<grid, THREADS, SMEM_TOTAL>>>(x, w1, b1, b2, w3, b3,
                                                   out, B, write_logits);
}

// round 7
// speedup vs baseline: 3.5585x; 1.2898x over previous
#include <cuda_runtime.h>
#include <cuda_fp16.h>
#include <cstdint>
#include <cstddef>
#include <math.h>

#define THREADS 512
#define MROWS   128

// smem byte offsets (dynamic)
#define OFF_X     0        // 1536
#define OFF_W1P   1536     // 4096
#define OFF_WC    5632     // 4096
#define OFF_ZP    9728     // 8192
#define OFF_A     18432    // 128 rows * 512 B = 65536
#define OFF_B     83968    // 2 bufs * 36864
#define BROW      144      // 128B data + 16B pad
#define BBUF      36864    // 256 * 144
#define SMEM_TOTAL 157696

__device__ __half g_w2h[65536];

__device__ __forceinline__ uint32_t smem_u32(const void* p) {
    uint32_t a;
    asm("{ .reg .u64 t; cvta.to.shared.u64 t, %1; cvt.u32.u64 %0, t; }" : "=r"(a) : "l"(p));
    return a;
}
__device__ __forceinline__ void cp_async16(uint32_t dst, const void* src) {
    asm volatile("cp.async.cg.shared.global [%0], [%1], 16;" :: "r"(dst), "l"(src) : "memory");
}
__device__ __forceinline__ void cp_commit() { asm volatile("cp.async.commit_group;" ::: "memory"); }
__device__ __forceinline__ void cp_wait1()  { asm volatile("cp.async.wait_group 1;" ::: "memory"); }
__device__ __forceinline__ void cp_wait0()  { asm volatile("cp.async.wait_group 0;" ::: "memory"); }

__device__ __forceinline__ void ldsm_x4(uint32_t* r, uint32_t addr) {
    asm volatile("ldmatrix.sync.aligned.m8n8.x4.shared.b16 {%0,%1,%2,%3}, [%4];"
                 : "=r"(r[0]), "=r"(r[1]), "=r"(r[2]), "=r"(r[3]) : "r"(addr));
}
__device__ __forceinline__ void mma_f16(float* d, const uint32_t* a, uint32_t b0, uint32_t b1) {
    asm volatile(
        "mma.sync.aligned.m16n8k16.row.col.f32.f16.f16.f32 "
        "{%0,%1,%2,%3}, {%4,%5,%6,%7}, {%8,%9}, {%0,%1,%2,%3};"
        : "+f"(d[0]), "+f"(d[1]), "+f"(d[2]), "+f"(d[3])
        : "r"(a[0]), "r"(a[1]), "r"(a[2]), "r"(a[3]), "r"(b0), "r"(b1));
}

// ---------------- pre-kernel: convert w2 to fp16 ----------------
__global__ void w2_half_kernel(const float* __restrict__ w2) {
    int i = blockIdx.x * 256 + threadIdx.x;
    g_w2h[i] = __float2half_rn(w2[i]);
}

// ---------------- main fused kernel ----------------
__global__ __launch_bounds__(THREADS, 1)
void dpl_hmma_kernel(const float* __restrict__ x,
                     const float* __restrict__ w1,
                     const float* __restrict__ b1,
                     const float* __restrict__ b2,
                     const float* __restrict__ w3,
                     const float* __restrict__ b3,
                     float* __restrict__ out,
                     int Btot, int write_logits)
{
    extern __shared__ char smc[];
    const uint32_t smu = smem_u32(smc);
    const int tid  = threadIdx.x;
    const int wid  = tid >> 5;
    const int lane = tid & 31;
    const int row0 = blockIdx.x * MROWS;

    const int rg  = wid & 3;       // row group: rows rg*32..+31
    const int cg  = wid >> 2;      // col group: cols cg*64..+63
    const int g   = lane >> 2;     // 0..7
    const int tig = lane & 3;      // 0..3

    // ---- stage params + x ----
    {
        float* sX = (float*)(smc + OFF_X);
        for (int i = tid; i < MROWS * 3; i += THREADS) {
            long gi = (long)row0 * 3 + i;
            sX[i] = (gi < (long)Btot * 3) ? x[gi] : 0.0f;
        }
        if (tid < 256) {
            ((float4*)(smc + OFF_W1P))[tid] =
                make_float4(w1[tid*3+0], w1[tid*3+1], w1[tid*3+2], b1[tid]);
            ((float4*)(smc + OFF_WC))[tid] =
                make_float4(b2[tid], w3[tid], w3[256+tid], w3[512+tid]);
        }
    }
    __syncthreads();

    // ---- preload B chunk 0 (overlaps with layer1 below) ----
    {
        #pragma unroll
        for (int it = 0; it < 4; it++) {
            int idx = tid + it * THREADS;     // 0..2047
            int n   = idx >> 3;
            int seg = idx & 7;
            cp_async16(smu + OFF_B + (uint32_t)(n * BROW + seg * 16),
                       (const char*)g_w2h + (size_t)n * 512 + seg * 16);
        }
        cp_commit();
    }

    // ---- layer 1 -> A fp16 tile (XOR-swizzled, conflict-free) ----
    {
        const float*  sX   = (const float*)(smc + OFF_X);
        const float4* sW1P = (const float4*)(smc + OFF_W1P);
        const int rb = (wid & 3) * 32 + (lane & 7);
        const int jb = (wid >> 2) * 64 + ((lane >> 3) << 1);
        const uint32_t xorv = (uint32_t)((lane & 7) << 4);
        #pragma unroll
        for (int s = 0; s < 4; s++) {
            const int r = rb + s * 8;
            const float x0 = sX[r*3+0], x1 = sX[r*3+1], x2 = sX[r*3+2];
            char* rowp = smc + OFF_A + r * 512;
            #pragma unroll
            for (int t = 0; t < 8; t++) {
                const int j = jb + t * 8;
                float4 wa = sW1P[j];
                float4 wb = sW1P[j+1];
                float f0 = fmaf(x0, wa.x, fmaf(x1, wa.y, fmaf(x2, wa.z, wa.w)));
                float f1 = fmaf(x0, wb.x, fmaf(x1, wb.y, fmaf(x2, wb.z, wb.w)));
                f0 = fmaxf(f0, 0.0f); f1 = fmaxf(f1, 0.0f);
                __half2 hw = __floats2half2_rn(f0, f1);
                const uint32_t off = (uint32_t)(j * 2) ^ xorv;
                *(uint32_t*)(rowp + off) = *(uint32_t*)&hw;
            }
        }
    }

    // ---- accumulators ----
    float acc[2][8][4];
    #pragma unroll
    for (int mt = 0; mt < 2; mt++)
        #pragma unroll
        for (int nt = 0; nt < 8; nt++)
            #pragma unroll
            for (int q = 0; q < 4; q++) acc[mt][nt][q] = 0.0f;

    // ---- per-lane ldmatrix addresses ----
    // A: lane l -> row rg*32 + (l&15) (+ mt*16), k-halve (l>>4)*16 bytes, swizzle XOR
    const int arow = rg * 32 + (lane & 15);
    const uint32_t aklane = (uint32_t)((lane >> 4) * 16);
    const uint32_t av = (uint32_t)((lane & 7) << 4);
    const uint32_t abase0 = smu + OFF_A + (uint32_t)(arow * 512);
    const uint32_t abase1 = abase0 + 16 * 512;
    // B: pair p, matrix m = lane>>3 (0:even-lo,1:even-hi,2:odd-lo,3:odd-hi), mrow = lane&7
    const int bm = lane >> 3;
    const int bmrow = lane & 7;
    uint32_t boff[4];
    #pragma unroll
    for (int p = 0; p < 4; p++) {
        const int nt = p * 2 + (bm >> 1);
        const int ncol = cg * 64 + nt * 8 + bmrow;
        boff[p] = (uint32_t)(ncol * BROW + (bm & 1) * 16);
    }

    // ---- main loop: 4 chunks of k=64 ----
    for (int c = 0; c < 4; c++) {
        if (c < 3) {
            const int nxt = c + 1;
            #pragma unroll
            for (int it = 0; it < 4; it++) {
                int idx = tid + it * THREADS;
                int n   = idx >> 3;
                int seg = idx & 7;
                cp_async16(smu + OFF_B + (uint32_t)((nxt & 1) * BBUF + n * BROW + seg * 16),
                           (const char*)g_w2h + (size_t)n * 512 + nxt * 128 + seg * 16);
            }
            cp_commit();
            cp_wait1();
        } else {
            cp_wait0();
        }
        __syncthreads();

        const uint32_t bbase = smu + OFF_B + (uint32_t)((c & 1) * BBUF);

        #pragma unroll
        for (int ks = 0; ks < 4; ks++) {
            const uint32_t kb = (uint32_t)(c * 128 + ks * 32);   // bytes along k
            const uint32_t aoff = (kb + aklane) ^ av;

            uint32_t a0[4], a1[4];
            ldsm_x4(a0, abase0 + aoff);
            ldsm_x4(a1, abase1 + aoff);

            uint32_t bfr[4][4];
            const uint32_t bks = (uint32_t)(ks * 32);
            ldsm_x4(bfr[0], bbase + boff[0] + bks);
            ldsm_x4(bfr[1], bbase + boff[1] + bks);
            ldsm_x4(bfr[2], bbase + boff[2] + bks);
            ldsm_x4(bfr[3], bbase + boff[3] + bks);

            #pragma unroll
            for (int p = 0; p < 4; p++) {
                mma_f16(acc[0][p*2  ], a0, bfr[p][0], bfr[p][1]);
                mma_f16(acc[1][p*2  ], a1, bfr[p][0], bfr[p][1]);
                mma_f16(acc[0][p*2+1], a0, bfr[p][2], bfr[p][3]);
                mma_f16(acc[1][p*2+1], a1, bfr[p][2], bfr[p][3]);
            }
        }
        __syncthreads();
    }

    // ---- epilogue: relu(+b2) + layer3 partials in registers ----
    const float4* sWC = (const float4*)(smc + OFF_WC);
    float z[4][3];
    #pragma unroll
    for (int i = 0; i < 4; i++) { z[i][0] = 0.f; z[i][1] = 0.f; z[i][2] = 0.f; }

    #pragma unroll
    for (int mt = 0; mt < 2; mt++) {
        #pragma unroll
        for (int nt = 0; nt < 8; nt++) {
            const int j0 = cg * 64 + nt * 8 + tig * 2;
            float4 wc0 = sWC[j0];
            float4 wc1 = sWC[j0 + 1];
            float h;
            h = fmaxf(acc[mt][nt][0] + wc0.x, 0.0f);
            z[mt*2][0] = fmaf(h, wc0.y, z[mt*2][0]);
            z[mt*2][1] = fmaf(h, wc0.z, z[mt*2][1]);
            z[mt*2][2] = fmaf(h, wc0.w, z[mt*2][2]);
            h = fmaxf(acc[mt][nt][1] + wc1.x, 0.0f);
            z[mt*2][0] = fmaf(h, wc1.y, z[mt*2][0]);
            z[mt*2][1] = fmaf(h, wc1.z, z[mt*2][1]);
            z[mt*2][2] = fmaf(h, wc1.w, z[mt*2][2]);
            h = fmaxf(acc[mt][nt][2] + wc0.x, 0.0f);
            z[mt*2+1][0] = fmaf(h, wc0.y, z[mt*2+1][0]);
            z[mt*2+1][1] = fmaf(h, wc0.z, z[mt*2+1][1]);
            z[mt*2+1][2] = fmaf(h, wc0.w, z[mt*2+1][2]);
            h = fmaxf(acc[mt][nt][3] + wc1.x, 0.0f);
            z[mt*2+1][0] = fmaf(h, wc1.y, z[mt*2+1][0]);
            z[mt*2+1][1] = fmaf(h, wc1.z, z[mt*2+1][1]);
            z[mt*2+1][2] = fmaf(h, wc1.w, z[mt*2+1][2]);
        }
    }
    // reduce across the 4 tig lanes of each quad
    #pragma unroll
    for (int i = 0; i < 4; i++)
        #pragma unroll
        for (int cmp = 0; cmp < 3; cmp++) {
            float v = z[i][cmp];
            v += __shfl_xor_sync(0xffffffffu, v, 1);
            v += __shfl_xor_sync(0xffffffffu, v, 2);
            z[i][cmp] = v;
        }

    if (tig == 0) {
        float4* sZP = (float4*)(smc + OFF_ZP);
        #pragma unroll
        for (int i = 0; i < 4; i++) {
            const int r = rg * 32 + (i >> 1) * 16 + (i & 1) * 8 + g;
            sZP[cg * 128 + r] = make_float4(z[i][0], z[i][1], z[i][2], 0.0f);
        }
    }
    __syncthreads();

    if (tid < MROWS) {
        const float4* sZP = (const float4*)(smc + OFF_ZP);
        float4 a0 = sZP[tid], a1 = sZP[128 + tid], a2 = sZP[256 + tid], a3 = sZP[384 + tid];
        float z0 = a0.x + a1.x + a2.x + a3.x + b3[0];
        float z1 = a0.y + a1.y + a2.y + a3.y + b3[1];
        float z2 = a0.z + a1.z + a2.z + a3.z + b3[2];

        const int gr = row0 + tid;
        if (gr < Btot) {
            const float eps  = 1e-5f;
            const float norm = 1.0f / (1.0f + 2.0f * eps);
            float s0 = 1.0f / (1.0f + expf(-z0));
            float s1 = 1.0f / (1.0f + expf(-z1));
            float s2 = 1.0f / (1.0f + expf(-z2));
            float pp0 = (s0 + eps) * norm, pn0 = (1.0f - s0 + eps) * norm;
            float pp1 = (s1 + eps) * norm, pn1 = (1.0f - s1 + eps) * norm;
            float pp2 = (s2 + eps) * norm, pn2 = (1.0f - s2 + eps) * norm;
            float pred1 = pn0*pn1*pp2 + pn0*pp1*pn2 + pp0*pn1*pn2 + pp0*pp1*pp2;
            float pred0 = 1.0f - pred1;
            const float onorm = 1.0f / 1.002f;
            float2 pr = make_float2((pred0 + 0.001f) * onorm, (pred1 + 0.001f) * onorm);
            *(float2*)&out[(size_t)gr * 2] = pr;
            if (write_logits) {
                float* outLg = &out[(size_t)2 * Btot + (size_t)gr * 3];
                outLg[0] = z0; outLg[1] = z1; outLg[2] = z2;
            }
        }
    }
}

extern "C" void kernel_launch(void* const* d_in, const int* in_sizes, int n_in,
                              void* d_out, int out_size)
{
    const float* x  = (const float*)d_in[0];
    const float* w1 = (const float*)d_in[1];
    const float* b1 = (const float*)d_in[2];
    const float* w2 = (const float*)d_in[3];
    const float* b2 = (const float*)d_in[4];
    const float* w3 = (const float*)d_in[5];
    const float* b3 = (const float*)d_in[6];
    float* out = (float*)d_out;

    const int B = in_sizes[0] / 3;
    const int write_logits = (out_size >= 5 * B) ? 1 : 0;

    w2_half_kernel<<<256, 256>>>(w2);

    cudaFuncSetAttribute(dpl_hmma_kernel,
                         cudaFuncAttributeMaxDynamicSharedMemorySize, SMEM_TOTAL);

    const int grid = (B + MROWS - 1) / MROWS;
    dpl_hmma_kernel<<<grid, THREADS, SMEM_TOTAL>>>(x, w1, b1, b2, w3, b3,
                                                   out, B, write_logits);
}